// round 6
// baseline (speedup 1.0000x reference)
#include <cuda_runtime.h>
#include <cuda_bf16.h>
#include <math.h>

// Problem constants
#define C 144
#define W 77
#define KW 10
#define FC 64
#define CONV_OUT 68                  // W - KW + 1
#define FC_N (C*FC)                  // 9216
#define CONCAT_N (FC_N + CONV_OUT)   // 9284
#define CONCAT_V4 (CONCAT_N/4)       // 2321
#define H2 128
#define CHUNK 581                    // ceil(2321/4)

#define GRID 592                     // 148 SMs x 4 CTAs, all resident
#define NWARPS (GRID*8)              // 4736

// Scratch (no allocations allowed)
__device__ __align__(16) float g_concat[CONCAT_N];
__device__ float g_part[H2 * 4];
__device__ int g_sync1;
__device__ int g_sync2;

__device__ __forceinline__ float warp_reduce(float v) {
    #pragma unroll
    for (int o = 16; o > 0; o >>= 1) v += __shfl_xor_sync(0xffffffffu, v, o);
    return v;
}

__device__ __forceinline__ void fc_one(const float* __restrict__ fc_w,
                                       const float* __restrict__ fc_b,
                                       const float* __restrict__ x,
                                       int o, int lane) {
    const int c = o >> 6;
    const float* __restrict__ wr = fc_w + (size_t)o * W;
    const float* __restrict__ xr = x + c * W;
    float s = wr[lane] * xr[lane] + wr[lane + 32] * xr[lane + 32];
    if (lane < 13) s += wr[lane + 64] * xr[lane + 64];
    s = warp_reduce(s);
    if (lane == 0) g_concat[o] = s + fc_b[o];
}

__global__ __launch_bounds__(256, 4) void fused_all(
    const float* __restrict__ x,       // [C, W]
    const float* __restrict__ fc_w,    // [C*FC, W]
    const float* __restrict__ fc_b,    // [C*FC]
    const float* __restrict__ conv_w,  // [C*KW] = 1440
    const float* __restrict__ conv_b,  // [1]
    const float* __restrict__ w2,      // [H2, CONCAT_N]
    const float* __restrict__ b2,      // [H2]
    const float* __restrict__ w3,      // [H2]
    const float* __restrict__ b3,      // [1]
    float* __restrict__ out)           // [1]
{
    const int blk = blockIdx.x;
    const int tid = threadIdx.x;
    const int warp = tid >> 5, lane = tid & 31;
    const int gw = blk * 8 + warp;     // 0..4735

    __shared__ float red[8];
    __shared__ int is_last;

    // ---------------- Phase 1: FC (9216 outputs) + conv (68 outputs) ----------------
    fc_one(fc_w, fc_b, x, gw, lane);                 // outputs 0..4735
    if (gw < FC_N - NWARPS) {                        // gw < 4480 -> outputs 4736..9215
        fc_one(fc_w, fc_b, x, gw + NWARPS, lane);
    } else if (gw < FC_N - NWARPS + CONV_OUT) {      // 68 warps do conv
        const int o = gw - (FC_N - NWARPS);          // 0..67
        float s = 0.f;
        int c = lane / KW, k = lane - (lane / KW) * KW;
        #pragma unroll
        for (int it = 0; it < 45; it++) {            // covers i = lane + 32*it < 1440
            s += conv_w[c * KW + k] * x[c * W + o + k];
            k += 2; c += 3;
            if (k >= KW) { k -= KW; c += 1; }
        }
        s = warp_reduce(s);
        if (lane == 0) g_concat[FC_N + o] = s + conv_b[0];
    }

    // ---------------- Grid barrier ----------------
    __threadfence();            // publish this thread's g_concat stores
    __syncthreads();
    if (tid == 0) {
        atomicAdd(&g_sync1, 1);
        while (*(volatile int*)&g_sync1 < GRID) __nanosleep(32);
        __threadfence();
    }
    __syncthreads();

    // ---------------- Phase 2: split-K GEMV (blocks 0..511) ----------------
    if (blk < 512) {
        const int j  = blk >> 2;       // row 0..127
        const int sp = blk & 3;        // chunk 0..3
        const int start = sp * CHUNK;
        const int end = (start + CHUNK < CONCAT_V4) ? start + CHUNK : CONCAT_V4;

        const float4* __restrict__ wrow = reinterpret_cast<const float4*>(w2 + (size_t)j * CONCAT_N);
        const float4* __restrict__ cc   = reinterpret_cast<const float4*>(g_concat);

        float s = 0.f;
        #pragma unroll 3
        for (int i = start + tid; i < end; i += 256) {
            const float4 a = wrow[i];
            const float4 c = cc[i];
            s += a.x * c.x + a.y * c.y + a.z * c.z + a.w * c.w;
        }
        s = warp_reduce(s);
        if (lane == 0) red[warp] = s;
        __syncthreads();
        if (tid == 0) {
            float t = red[0];
            #pragma unroll
            for (int q = 1; q < 8; q++) t += red[q];
            g_part[j * 4 + sp] = t;
        }
    }

    // ---------------- Completion + head ----------------
    if (tid == 0) {
        __threadfence();
        const int n = atomicAdd(&g_sync2, 1);
        is_last = (n == GRID - 1) ? 1 : 0;
    }
    __syncthreads();

    if (is_last && warp == 0) {
        __threadfence();
        float acc = 0.f;
        #pragma unroll
        for (int q = 0; q < 4; q++) {
            const int r = lane + q * 32;
            const float v = g_part[r * 4 + 0] + g_part[r * 4 + 1]
                          + g_part[r * 4 + 2] + g_part[r * 4 + 3];
            const float h = fmaxf(v + b2[r], 0.f);
            acc += w3[r] * h;
        }
        acc = warp_reduce(acc);
        if (lane == 0) {
            acc = fmaxf(acc + b3[0], 0.f);
            out[0] = 1.f / (1.f + expf(-acc));
            g_sync1 = 0;               // reset for next replay
            g_sync2 = 0;
        }
    }
}

extern "C" void kernel_launch(void* const* d_in, const int* in_sizes, int n_in,
                              void* d_out, int out_size) {
    const float* x      = (const float*)d_in[0];
    const float* fc_w   = (const float*)d_in[1];
    const float* fc_b   = (const float*)d_in[2];
    const float* conv_w = (const float*)d_in[3];
    const float* conv_b = (const float*)d_in[4];
    const float* w2     = (const float*)d_in[5];
    const float* b2     = (const float*)d_in[6];
    const float* w3     = (const float*)d_in[7];
    const float* b3     = (const float*)d_in[8];
    float* out = (float*)d_out;

    fused_all<<<GRID, 256>>>(x, fc_w, fc_b, conv_w, conv_b, w2, b2, w3, b3, out);
}